// round 13
// baseline (speedup 1.0000x reference)
#include <cuda_runtime.h>
#include <cstdint>

#define BATCH 512
#define TLEN  1024
#define NST   64

typedef unsigned long long ull;

// Packed f32x2 helpers (Blackwell FFMA2 path — only reachable via PTX f32x2)
#define FMA2(d, a, b, c) asm("fma.rn.f32x2 %0, %1, %2, %3;" : "=l"(d) : "l"(a), "l"(b), "l"(c))
#define ADD2(d, a, b)    asm("add.rn.f32x2 %0, %1, %2;"     : "=l"(d) : "l"(a), "l"(b))
#define UNPACK2(lo, hi, s) asm("mov.b64 {%0, %1}, %2;"      : "=f"(lo), "=f"(hi) : "l"(s))

// Per-chain named barrier, alternating HW barrier ids by step parity
#define CHAIN_BAR_ID(id) asm volatile("bar.sync %0, 64;" :: "r"(id) : "memory")

__device__ __forceinline__ float fexp(float x) {
    float y;
    asm("ex2.approx.f32 %0, %1;" : "=f"(y) : "f"(x * 1.4426950408889634f));
    return y;
}
__device__ __forceinline__ float ex2f(float x) {
    float y;
    asm("ex2.approx.f32 %0, %1;" : "=f"(y) : "f"(x));
    return y;
}
__device__ __forceinline__ float flog(float x) {
    float y;
    asm("lg2.approx.f32 %0, %1;" : "=f"(y) : "f"(x));
    return y * 0.6931471805599453f;
}

// chain index by descending-length rank
__device__ int g_perm[BATCH];

// Bitonic argsort of lengths (ascending), then store descending perm.
// Keys are (len<<16)|idx -> unique -> fully deterministic.
__global__ void sort_kernel(const int* __restrict__ lengths) {
    __shared__ unsigned key[BATCH];
    int t = threadIdx.x;
    int len = lengths[t];
    if (len < 1) len = 1;
    key[t] = ((unsigned)len << 16) | (unsigned)t;
    __syncthreads();
    for (int k = 2; k <= BATCH; k <<= 1) {
        for (int j = k >> 1; j > 0; j >>= 1) {
            int ix = t ^ j;
            if (ix > t) {
                unsigned a = key[t], b = key[ix];
                bool up = ((t & k) == 0);
                if (up ? (a > b) : (a < b)) { key[t] = b; key[ix] = a; }
            }
            __syncthreads();
        }
    }
    g_perm[BATCH - 1 - t] = (int)(key[t] & 0xFFFFu);  // descending by length
}

// grid=128, block=256: ONE CTA per SM. 4 chains/CTA; chain q = warps {2q,2q+1}.
// Anti-paired ranks: each SMSP pair hosts (long, short) -> long chain runs solo.
// Loop body branch-free: every-step power-of-2 renorm via lag-2 smem ring.
// Alternating named-barrier ids pipeline barrier drain across steps.
__global__ void __launch_bounds__(256, 1) crf_kernel(
    const float* __restrict__ unary,
    const int*   __restrict__ lengths,
    const float* __restrict__ trans,
    float*       __restrict__ out)
{
    const int tid  = threadIdx.x;
    const int q    = tid >> 6;           // chain slot 0..3
    const int t64  = tid & 63;           // thread within chain
    const int hw   = t64 >> 5;           // warp-half within chain (0/1)
    const int lane = tid & 31;
    const int c    = t64;                // my column

    // rank -> chain index (anti-paired scheduling)
    const int i = blockIdx.x;
    int rank;
    if (q == 0)      rank = 2 * i;                 // longest in CTA
    else if (q == 1) rank = 2 * i + 1;
    else if (q == 2) rank = (BATCH - 1) - 2 * i;   // shortest
    else             rank = (BATCH - 2) - 2 * i;
    const int b = g_perm[rank];

    // E column slice computed inline:
    // cE[k] = ( exp(trans[2k][c]), exp(trans[2k+1][c]) ), 32 packed i-pairs
    ull cE[32];
    #pragma unroll
    for (int k = 0; k < 32; k++) {
        float e0 = expf(trans[(2 * k) * NST + c]);
        float e1 = expf(trans[(2 * k + 1) * NST + c]);
        ull pk;
        asm("mov.b64 %0, {%1, %2};" : "=l"(pk) : "f"(e0), "f"(e1));
        cE[k] = pk;
    }

    __shared__ __align__(16) float wbuf[4][2][NST];  // [chain][buf][col]
    __shared__ int   sexp[4][4];                      // [chain][t&3] exponent ring
    __shared__ float ssum[4][2];                      // [chain][warp-half]

    int len = lengths[b];
    if (len < 1) len = 1;
    const float* ub = unary + (size_t)b * (TLEN * NST);
    const float* pc = ub + c;

    // w0 = exp(u0); init exponent ring to 0 (reads at t=1,2 hit untouched slots)
    float w = fexp(pc[0]);
    wbuf[q][0][c] = w;
    if (t64 == 0) { sexp[q][0] = 0; sexp[q][1] = 0; sexp[q][2] = 0; sexp[q][3] = 0; }

    int ktot = 0;
    // distance-3 register prefetch pipeline of this thread's unary column
    float uA = 0.f, uB = 0.f, uC = 0.f;
    if (len > 1) uA = pc[NST];
    uB = (len > 2) ? pc[2 * NST] : uA;
    uC = (len > 3) ? pc[3 * NST] : uB;
    const float* up = pc + (size_t)((len - 1 < 4) ? (len - 1) : 4) * NST;

    const float L2E = 1.4426950408889634f;
    int buf = 0;
    const int barA = 1 + q;   // odd t
    const int barB = 5 + q;   // even t

    for (int t = 1; t < len; t++) {
        if (t & 1) CHAIN_BAR_ID(barA); else CHAIN_BAR_ID(barB);

        // lag-2 renorm apply, every step, branch-free (write was 2 barriers ago)
        int e = sexp[q][(t + 2) & 3];   // == (t-2)&3
        ktot += e;
        float eu = ex2f(fmaf(uA, L2E, -(float)e));  // MUFU off critical path

        // matvec for my column: 16 broadcast LDS.128 + 32 FFMA2, 8 accumulators
        const ulonglong2* P = (const ulonglong2*)wbuf[q][buf];
        ull a0 = 0ull, a1 = 0ull, a2 = 0ull, a3 = 0ull;
        ull a4 = 0ull, a5 = 0ull, a6 = 0ull, a7 = 0ull;
        #pragma unroll
        for (int m = 0; m < 16; m += 4) {
            ulonglong2 x = P[m];
            ulonglong2 y = P[m + 1];
            ulonglong2 z = P[m + 2];
            ulonglong2 v = P[m + 3];
            FMA2(a0, x.x, cE[2 * m + 0], a0);
            FMA2(a1, x.y, cE[2 * m + 1], a1);
            FMA2(a2, y.x, cE[2 * m + 2], a2);
            FMA2(a3, y.y, cE[2 * m + 3], a3);
            FMA2(a4, z.x, cE[2 * m + 4], a4);
            FMA2(a5, z.y, cE[2 * m + 5], a5);
            FMA2(a6, v.x, cE[2 * m + 6], a6);
            FMA2(a7, v.y, cE[2 * m + 7], a7);
        }
        ADD2(a0, a0, a1);
        ADD2(a2, a2, a3);
        ADD2(a4, a4, a5);
        ADD2(a6, a6, a7);
        ADD2(a0, a0, a2);
        ADD2(a4, a4, a6);
        ADD2(a0, a0, a4);
        float slo, shi;
        UNPACK2(slo, shi, a0);
        w = (slo + shi) * eu;

        // publish w IMMEDIATELY (peer's barrier release depends on this STS)
        wbuf[q][buf ^ 1][c] = w;

        // exponent publish, every step, predicated single STS (no BSSY)
        int myE = ((__float_as_int(w) >> 23) & 255) - 127;
        myE = min(max(myE, -100), 100);
        if (c == 0) sexp[q][t & 3] = myE;

        // shift unary pipeline (distance 3); selp-guarded pointer walk
        uA = uB; uB = uC;
        uC = *up;
        up += (t + 4 < len) ? NST : 0;

        buf ^= 1;
    }

    // out[b] = ktot*ln2 + log(sum_j w_j): warp reduce, combine 2 warps via smem
    float s = w;
    #pragma unroll
    for (int off = 16; off; off >>= 1)
        s += __shfl_xor_sync(0xffffffffu, s, off);
    if (lane == 0) ssum[q][hw] = s;
    CHAIN_BAR_ID(barA);
    if (c == 0)
        out[b] = (float)ktot * 0.6931471805599453f + flog(ssum[q][0] + ssum[q][1]);
}

extern "C" void kernel_launch(void* const* d_in, const int* in_sizes, int n_in,
                              void* d_out, int out_size) {
    const float* unary   = nullptr;
    const int*   lengths = nullptr;
    const float* trans   = nullptr;
    for (int i = 0; i < n_in; i++) {
        if (in_sizes[i] == BATCH * TLEN * NST) unary   = (const float*)d_in[i];
        else if (in_sizes[i] == BATCH)         lengths = (const int*)d_in[i];
        else if (in_sizes[i] == NST * NST)     trans   = (const float*)d_in[i];
    }
    sort_kernel<<<1, BATCH>>>(lengths);
    crf_kernel<<<BATCH / 4, 256>>>(unary, lengths, trans, (float*)d_out);
}

// round 14
// speedup vs baseline: 1.1353x; 1.1353x over previous
#include <cuda_runtime.h>
#include <cstdint>

#define BATCH 512
#define TLEN  1024
#define NST   64

typedef unsigned long long ull;

// Packed f32x2 helpers (Blackwell FFMA2 path — only reachable via PTX f32x2)
#define FMA2(d, a, b, c) asm("fma.rn.f32x2 %0, %1, %2, %3;" : "=l"(d) : "l"(a), "l"(b), "l"(c))
#define ADD2(d, a, b)    asm("add.rn.f32x2 %0, %1, %2;"     : "=l"(d) : "l"(a), "l"(b))
#define UNPACK2(lo, hi, s) asm("mov.b64 {%0, %1}, %2;"      : "=f"(lo), "=f"(hi) : "l"(s))

#define CHAIN_BAR(q) asm volatile("bar.sync %0, 64;" :: "r"(1 + (q)) : "memory")

__device__ __forceinline__ float fexp(float x) {
    float y;
    asm("ex2.approx.f32 %0, %1;" : "=f"(y) : "f"(x * 1.4426950408889634f));
    return y;
}
__device__ __forceinline__ float ex2f(float x) {
    float y;
    asm("ex2.approx.f32 %0, %1;" : "=f"(y) : "f"(x));
    return y;
}
__device__ __forceinline__ float flog(float x) {
    float y;
    asm("lg2.approx.f32 %0, %1;" : "=f"(y) : "f"(x));
    return y * 0.6931471805599453f;
}

// chain index by descending-length rank
__device__ int g_perm[BATCH];

// Bitonic argsort of lengths (ascending), then store descending perm.
__global__ void sort_kernel(const int* __restrict__ lengths) {
    __shared__ unsigned key[BATCH];
    int t = threadIdx.x;
    int len = lengths[t];
    if (len < 1) len = 1;
    key[t] = ((unsigned)len << 16) | (unsigned)t;
    __syncthreads();
    for (int k = 2; k <= BATCH; k <<= 1) {
        for (int j = k >> 1; j > 0; j >>= 1) {
            int ix = t ^ j;
            if (ix > t) {
                unsigned a = key[t], b = key[ix];
                bool up = ((t & k) == 0);
                if (up ? (a > b) : (a < b)) { key[t] = b; key[ix] = a; }
            }
            __syncthreads();
        }
    }
    g_perm[BATCH - 1 - t] = (int)(key[t] & 0xFFFFu);  // descending by length
}

// 16 broadcast LDS.128 + 32 FFMA2, 8 accumulators (R12 matvec, verbatim)
__device__ __forceinline__ float matvec_col(const ulonglong2* __restrict__ P,
                                            const ull* __restrict__ cE) {
    ull a0 = 0ull, a1 = 0ull, a2 = 0ull, a3 = 0ull;
    ull a4 = 0ull, a5 = 0ull, a6 = 0ull, a7 = 0ull;
    #pragma unroll
    for (int m = 0; m < 16; m += 4) {
        ulonglong2 x = P[m];
        ulonglong2 y = P[m + 1];
        ulonglong2 z = P[m + 2];
        ulonglong2 v = P[m + 3];
        FMA2(a0, x.x, cE[2 * m + 0], a0);
        FMA2(a1, x.y, cE[2 * m + 1], a1);
        FMA2(a2, y.x, cE[2 * m + 2], a2);
        FMA2(a3, y.y, cE[2 * m + 3], a3);
        FMA2(a4, z.x, cE[2 * m + 4], a4);
        FMA2(a5, z.y, cE[2 * m + 5], a5);
        FMA2(a6, v.x, cE[2 * m + 6], a6);
        FMA2(a7, v.y, cE[2 * m + 7], a7);
    }
    ADD2(a0, a0, a1);
    ADD2(a2, a2, a3);
    ADD2(a4, a4, a5);
    ADD2(a6, a6, a7);
    ADD2(a0, a0, a2);
    ADD2(a4, a4, a6);
    ADD2(a0, a0, a4);
    float slo, shi;
    UNPACK2(slo, shi, a0);
    return slo + shi;
}

// grid=128, block=256: ONE CTA per SM. 4 chains/CTA; chain q = warps {2q,2q+1}.
// Anti-paired ranks -> long chain runs solo on its SMSP pair (R8/R12 structure).
// Main loop unrolled x4 with phase-specialized steps: hardcoded buffers,
// renorm apply only in phase B (t%4==2), exponent publish only in phase D (t%4==0).
__global__ void __launch_bounds__(256, 1) crf_kernel(
    const float* __restrict__ unary,
    const int*   __restrict__ lengths,
    const float* __restrict__ trans,
    float*       __restrict__ out)
{
    const int tid  = threadIdx.x;
    const int q    = tid >> 6;           // chain slot 0..3
    const int t64  = tid & 63;           // thread within chain
    const int hw   = t64 >> 5;           // warp-half within chain (0/1)
    const int lane = tid & 31;
    const int c    = t64;                // my column

    // rank -> chain index (anti-paired scheduling)
    const int i = blockIdx.x;
    int rank;
    if (q == 0)      rank = 2 * i;                 // longest in CTA
    else if (q == 1) rank = 2 * i + 1;
    else if (q == 2) rank = (BATCH - 1) - 2 * i;   // shortest
    else             rank = (BATCH - 2) - 2 * i;
    const int b = g_perm[rank];

    // E column slice computed inline: 32 packed i-pairs
    ull cE[32];
    #pragma unroll
    for (int k = 0; k < 32; k++) {
        float e0 = expf(trans[(2 * k) * NST + c]);
        float e1 = expf(trans[(2 * k + 1) * NST + c]);
        ull pk;
        asm("mov.b64 %0, {%1, %2};" : "=l"(pk) : "f"(e0), "f"(e1));
        cE[k] = pk;
    }

    __shared__ __align__(16) float wbuf[4][2][NST];  // [chain][buf][col]
    __shared__ int   sexp[4];                         // [chain] lag-2 exponent
    __shared__ float ssum[4][2];                      // [chain][warp-half]

    int len = lengths[b];
    if (len < 1) len = 1;
    const float* ub = unary + (size_t)b * (TLEN * NST);
    const float* pc = ub + c;

    // w0 = exp(u0); sexp init 0 so phase-B applies are no-ops until first publish
    float w = fexp(pc[0]);
    wbuf[q][0][c] = w;
    if (t64 == 0) sexp[q] = 0;

    int ktot = 0;
    // distance-3 register prefetch pipeline of this thread's unary column
    float uA = 0.f, uB = 0.f, uC = 0.f;
    if (len > 1) uA = pc[NST];
    uB = (len > 2) ? pc[2 * NST] : uA;
    uC = (len > 3) ? pc[3 * NST] : uB;
    const float* up = pc + (size_t)((len - 1 < 4) ? (len - 1) : 4) * NST;

    const float L2E = 1.4426950408889634f;

    // hardcoded buffer pointers (no per-step address math)
    const ulonglong2* PB0 = (const ulonglong2*)wbuf[q][0];
    const ulonglong2* PB1 = (const ulonglong2*)wbuf[q][1];
    float* W0 = &wbuf[q][0][c];
    float* W1 = &wbuf[q][1][c];

    int t = 1;
    // ---- main loop: 4 steps per iteration, phase-specialized ----
    for (; t + 3 < len; t += 4) {
        // phase A (t%4==1): read buf0 -> write buf1
        CHAIN_BAR(q);
        {
            float eu = ex2f(uA * L2E);
            w = matvec_col(PB0, cE) * eu;
            *W1 = w;
            uA = uB; uB = uC; uC = *up;
            up += (t + 4 < len) ? NST : 0;
        }
        // phase B (t%4==2): APPLY renorm; read buf1 -> write buf0
        CHAIN_BAR(q);
        {
            int e = sexp[q];
            ktot += e;
            float eu = ex2f(fmaf(uA, L2E, -(float)e));
            w = matvec_col(PB1, cE) * eu;
            *W0 = w;
            uA = uB; uB = uC; uC = *up;
            up += (t + 5 < len) ? NST : 0;
        }
        // phase C (t%4==3): read buf0 -> write buf1
        CHAIN_BAR(q);
        {
            float eu = ex2f(uA * L2E);
            w = matvec_col(PB0, cE) * eu;
            *W1 = w;
            uA = uB; uB = uC; uC = *up;
            up += (t + 6 < len) ? NST : 0;
        }
        // phase D (t%4==0): PUBLISH exponent; read buf1 -> write buf0
        CHAIN_BAR(q);
        {
            float eu = ex2f(uA * L2E);
            w = matvec_col(PB1, cE) * eu;
            *W0 = w;
            int myE = ((__float_as_int(w) >> 23) & 255) - 127;
            myE = min(max(myE, -100), 100);
            if (c == 0) sexp[q] = myE;
            uA = uB; uB = uC; uC = *up;
            up += (t + 7 < len) ? NST : 0;
        }
    }

    // ---- epilogue: <=3 steps, general form (keeps phase behavior) ----
    int buf = 0;  // main loop always ends writing buf0
    for (; t < len; t++) {
        CHAIN_BAR(q);
        float kf = 0.0f;
        if ((t & 3) == 2) {
            int e = sexp[q];
            ktot += e;
            kf = (float)e;
        }
        float eu = ex2f(fmaf(uA, L2E, -kf));
        const ulonglong2* P = buf ? PB1 : PB0;
        w = matvec_col(P, cE) * eu;
        if ((t & 3) == 0 && c == 0) {
            int e2 = ((__float_as_int(w) >> 23) & 255) - 127;
            e2 = min(max(e2, -100), 100);
            sexp[q] = e2;
        }
        (buf ? W0 : W1)[0] = w;
        uA = uB; uB = uC;
        uC = *up;
        up += (t + 4 < len) ? NST : 0;
        buf ^= 1;
    }

    // out[b] = ktot*ln2 + log(sum_j w_j): warp reduce, combine 2 warps via smem
    float s = w;
    #pragma unroll
    for (int off = 16; off; off >>= 1)
        s += __shfl_xor_sync(0xffffffffu, s, off);
    if (lane == 0) ssum[q][hw] = s;
    CHAIN_BAR(q);
    if (c == 0)
        out[b] = (float)ktot * 0.6931471805599453f + flog(ssum[q][0] + ssum[q][1]);
}

extern "C" void kernel_launch(void* const* d_in, const int* in_sizes, int n_in,
                              void* d_out, int out_size) {
    const float* unary   = nullptr;
    const int*   lengths = nullptr;
    const float* trans   = nullptr;
    for (int i = 0; i < n_in; i++) {
        if (in_sizes[i] == BATCH * TLEN * NST) unary   = (const float*)d_in[i];
        else if (in_sizes[i] == BATCH)         lengths = (const int*)d_in[i];
        else if (in_sizes[i] == NST * NST)     trans   = (const float*)d_in[i];
    }
    sort_kernel<<<1, BATCH>>>(lengths);
    crf_kernel<<<BATCH / 4, 256>>>(unary, lengths, trans, (float*)d_out);
}